// round 15
// baseline (speedup 1.0000x reference)
#include <cuda_runtime.h>
#include <cstdint>

// ---------------- problem constants ----------------
#define AN      3
#define NC      80
#define NCH     85          // C+5
#define HH      52
#define WW      52
#define HWSZ    (HH*WW)     // 2704
#define MAXN    256
#define ROWF4   13          // 52 floats / 4
#define TILEF   (NCH*WW)    // 4420 floats per row
#define DTILEF  (2*TILEF)   // 8840 floats per 2-row tile
#define TMAIN   512
#define NWORK   444
#define NDT     1248        // 2-row tiles total
#define CELLS   (16*AN*HWSZ)
#define DTILE_BYTES (DTILEF*4)   // 35360
#define SMEM_DYN    (2*DTILE_BYTES)  // 70720 double buffer
#define SPEC0   447              // threads 447..511: special units (65/row)

__constant__ float c_aw[AN] = {10.f, 16.f, 33.f};
__constant__ float c_ah[AN] = {13.f, 30.f, 23.f};

// ---------------- device scratch (no allocations allowed) ----------------
__device__ int    g_mask_i[CELLS];
__device__ float  g_psum[NWORK];
__device__ float  g_fin[9];          // sx,sy,sw,sh,conf,cls,fsub,nobj,mcnt
__device__ unsigned int g_done;      // zero at load; winner resets each replay

// ---- fast math helpers ----
#define L2E 1.4426950408889634f
#define LN2 0.6931471805599453f

__device__ __forceinline__ float fex2(float x) {
    float r; asm("ex2.approx.ftz.f32 %0, %1;" : "=f"(r) : "f"(x)); return r;
}
__device__ __forceinline__ float frcp(float x) {
    float r; asm("rcp.approx.ftz.f32 %0, %1;" : "=f"(r) : "f"(x)); return r;
}
__device__ __forceinline__ float flg2(float x) {
    float r; asm("lg2.approx.ftz.f32 %0, %1;" : "=f"(r) : "f"(x)); return r;
}
__device__ __forceinline__ float fsig(float z) { return frcp(1.0f + fex2(-L2E * z)); }
__device__ __forceinline__ float fexp(float z) { return fex2(L2E * z); }

__device__ __forceinline__ uint32_t smem_u32(const void* p) {
    return (uint32_t)__cvta_generic_to_shared(p);
}

// process one bulk float4 -> 4 sigmoids into smem ([w][c] layout)
__device__ __forceinline__ void bulk4(float* trow, int sb, float4 v) {
    trow[sb]           = fsig(v.x);
    trow[sb + NCH]     = fsig(v.y);
    trow[sb + 2 * NCH] = fsig(v.z);
    trow[sb + 3 * NCH] = fsig(v.w);
}

// ================= single fused kernel =================
__global__ __launch_bounds__(TMAIN, 3) void k_all(const float* __restrict__ x,
                                                  const float* __restrict__ t,
                                                  float* __restrict__ out,
                                                  int N, int ncells, int out_size) {
    extern __shared__ float buf[];       // 2 x 35360 B double buffer
    __shared__ float s_red[16];
    __shared__ int   s_misc;

    const int tid = threadIdx.x;
    const int bx0 = blockIdx.x;

    if (bx0 == 0) {
        // ======== setup block: targets + all x-only loss terms ========
        __shared__ float acc[8];
        __shared__ int   s_cnt[2];       // mcnt, nobj
        const int n = tid;
        if (n < 8) acc[n] = 0.0f;
        if (n < 2) s_cnt[n] = 0;
        __syncthreads();

        int   cells[4] = {-1, -1, -1, -1};
        int   mycell = -1;
        float ttx = 0.f, tty = 0.f, ttw = 0.f, tth = 0.f;
        int   lab = 0;

        if (n < N) {
            const float* tn = t + 6 * n;
            int   img = (int)tn[0];
            float gx = tn[1] * (float)WW;
            float gy = tn[2] * (float)HH;
            float gw = tn[3] * (float)WW;
            float gh = tn[4] * (float)HH;
            lab = (int)tn[5];

            float iou[AN];
            int best = 0;
            #pragma unroll
            for (int a = 0; a < AN; a++) {
                float aw2 = c_aw[a], ah2 = c_ah[a];
                float inter = fminf(aw2, gw) * fminf(ah2, gh);
                iou[a] = inter / (aw2 * ah2 + 1e-16f + gw * gh - inter);
            }
            if (iou[1] > iou[best]) best = 1;
            if (iou[2] > iou[best]) best = 2;

            int gi = (int)gx;
            int gj = (int)gy;
            mycell = ((img * AN + best) * HH + gj) * WW + gi;

            ttx = gx - floorf(gx);
            tty = gy - floorf(gy);
            ttw = logf(gw / c_aw[best] + 1e-16f);
            tth = logf(gh / c_ah[best] + 1e-16f);

            cells[0] = mycell;
            #pragma unroll
            for (int a = 0; a < AN; a++)
                if (iou[a] > 0.5f)
                    cells[a + 1] = ((img * AN + a) * HH + gj) * WW + gi;

            #pragma unroll
            for (int k = 0; k < 4; k++)
                if (cells[k] >= 0) g_mask_i[cells[k]] = 0;   // re-init each replay
        }
        __syncthreads();

        // unique-masked dedupe + complement subtraction (lg2 units)
        float fsub = 0.0f;
        if (n < N) {
            #pragma unroll
            for (int k = 0; k < 4; k++) {
                if (cells[k] >= 0 && atomicExch(&g_mask_i[cells[k]], 1) == 0) {
                    atomicAdd(&s_cnt[0], 1);
                    int cell = cells[k];
                    int i  = cell % WW;
                    int j  = (cell / WW) % HH;
                    int aa = (cell / HWSZ) % AN;
                    int bb = cell / (AN * HWSZ);
                    float z4 = x[((size_t)((bb * AN + aa) * NCH) + 4) * HWSZ
                                 + (size_t)j * WW + i];
                    fsub += flg2(1.0f - fsig(z4));
                }
            }
        }
        #pragma unroll
        for (int off = 16; off; off >>= 1)
            fsub += __shfl_down_sync(0xffffffffu, fsub, off);
        if ((tid & 31) == 0) s_red[tid >> 5] = fsub;
        __syncthreads();

        // obj-cell last-write-wins dedupe
        if (n < N) atomicMax(&g_mask_i[mycell], 2 + n);
        __syncthreads();

        // obj-cell losses (winners only)
        if (n < N && g_mask_i[mycell] == 2 + n) {
            int cell = mycell;
            int i  = cell % WW;
            int j  = (cell / WW) % HH;
            int aa = (cell / HWSZ) % AN;
            int bb = cell / (AN * HWSZ);
            const float* xb2 = x + ((size_t)(bb * AN + aa) * NCH) * HWSZ
                                 + (size_t)j * WW + i;
            float z0 = xb2[0];
            float z2 = xb2[(size_t)2 * HWSZ];
            float z4 = xb2[(size_t)4 * HWSZ];
            float cx = fsig(z0);
            float dx = cx - ttx;
            float dy = cx - tty;              // reference bug: y-loss uses cx
            float dw = z2 - ttw;
            float dh = z2 - tth;              // reference bug: h-loss uses pw
            float p4 = fmaxf(fsig(z4), 1e-12f);
            float conf = -flg2(p4) * LN2;     // t=1 at obj cell
            float cls = 0.0f;
            #pragma unroll 8
            for (int c = 0; c < NC; c++) {
                float p = fmaxf(fsig(xb2[(size_t)(5 + c) * HWSZ]), 1e-12f);
                cls -= (c == lab) ? flg2(p) * LN2 : flg2(1.0f - p) * LN2;
            }
            atomicAdd(&acc[0], dx * dx);
            atomicAdd(&acc[1], dy * dy);
            atomicAdd(&acc[2], dw * dw);
            atomicAdd(&acc[3], dh * dh);
            atomicAdd(&acc[4], conf);
            atomicAdd(&acc[5], cls);
            atomicAdd(&s_cnt[1], 1);
        }
        __syncthreads();
        if (tid == 0) {
            float fs = 0.0f;
            #pragma unroll
            for (int w = 0; w < 16; w++) fs += s_red[w];
            g_fin[0] = acc[0]; g_fin[1] = acc[1]; g_fin[2] = acc[2];
            g_fin[3] = acc[3]; g_fin[4] = acc[4]; g_fin[5] = acc[5];
            g_fin[6] = fs;                        // fsub (lg2 units)
            g_fin[7] = (float)s_cnt[1];           // nobj
            g_fin[8] = (float)s_cnt[0];           // mcnt
        }
    } else {
        // ======== worker: 2-3 double-row tiles, double-buffered bulk stores ====
        const int bx = bx0 - 1;                 // 0..443
        // blocks 0..359: 3 dtiles; 360..443: 2 dtiles (360*3 + 84*2 = 1248)
        const int three = (bx < 360);
        const int cnt = three ? 3 : 2;
        int D = three ? bx * 3 : 1080 + (bx - 360) * 2;

        // per-row bulk decomposition (row-units 0..1039; c>=5)
        int c0 = 5 + tid / ROWF4;
        int w0q = (tid - (c0 - 5) * ROWF4) * 4;
        int g1 = tid + 447;
        int c1 = 5 + g1 / ROWF4;
        int w1q = (g1 - (c1 - 5) * ROWF4) * 4;
        int g2 = tid + 894;
        int c2 = 5 + g2 / ROWF4;
        int w2q = (g2 - (c2 - 5) * ROWF4) * 4;
        const bool hasX = (tid < 146);          // row-units 894..1039
        const bool isSpec = (tid >= SPEC0);

        const int off0 = c0 * HWSZ + w0q;
        const int off1 = c1 * HWSZ + w1q;
        const int off2 = c2 * HWSZ + w2q;
        const int sb0 = w0q * NCH + c0;
        const int sb1 = w1q * NCH + c1;
        const int sb2 = w2q * NCH + c2;

        // special units: s in [0,65), scc = s/13, sw = (s%13)*4; both rows
        const int s = tid - SPEC0;
        const int scc = s / ROWF4;
        const int sw0 = (s - scc * ROWF4) * 4;
        const int offS = scc * HWSZ + sw0;
        const int sbS = sw0 * NCH + scc;

        float lsum = 0.0f;

        int h0 = (D % 26) * 2;                  // first row of dtile within plane
        int p  = D / 26;                        // plane = b*3+a
        const float* src = x + (size_t)p * (NCH * HWSZ) + (size_t)h0 * WW;
        float* gdst = out + (size_t)D * DTILEF;

        for (int it = 0; it < cnt; it++) {
            float* dbuf = buf + (it & 1) * DTILEF;

            if (tid == 0 && it >= 2)
                asm volatile("cp.async.bulk.wait_group 1;" ::: "memory");
            __syncthreads();

            if (!isSpec) {
                // ---- row 0 ----
                {
                    float4 v0 = *reinterpret_cast<const float4*>(src + off0);
                    float4 v1 = *reinterpret_cast<const float4*>(src + off1);
                    float4 v2;
                    if (hasX) v2 = *reinterpret_cast<const float4*>(src + off2);
                    bulk4(dbuf, sb0, v0);
                    bulk4(dbuf, sb1, v1);
                    if (hasX) bulk4(dbuf, sb2, v2);
                }
                // ---- row 1 ----
                {
                    const float* s1 = src + WW;
                    float* t1 = dbuf + TILEF;
                    float4 v0 = *reinterpret_cast<const float4*>(s1 + off0);
                    float4 v1 = *reinterpret_cast<const float4*>(s1 + off1);
                    float4 v2;
                    if (hasX) v2 = *reinterpret_cast<const float4*>(s1 + off2);
                    bulk4(t1, sb0, v0);
                    bulk4(t1, sb1, v1);
                    if (hasX) bulk4(t1, sb2, v2);
                }
            } else {
                // ---- special: both rows, branchy (65 threads only) ----
                float4 sv0 = *reinterpret_cast<const float4*>(src + offS);
                float4 sv1 = *reinterpret_cast<const float4*>(src + WW + offS);
                const int a = p - (p / AN) * AN;     // p % 3
                const float aw = c_aw[a], ah = c_ah[a];
                #pragma unroll
                for (int r = 0; r < 2; r++) {
                    float4 sv = r ? sv1 : sv0;
                    float* trow = dbuf + r * TILEF;
                    const float hf = (float)(h0 + r);
                    float e0, e1, e2, e3;
                    if (scc == 0) {
                        e0 = (fsig(sv.x) + (float)sw0) * 8.0f;
                        e1 = (fsig(sv.y) + (float)(sw0 + 1)) * 8.0f;
                        e2 = (fsig(sv.z) + (float)(sw0 + 2)) * 8.0f;
                        e3 = (fsig(sv.w) + (float)(sw0 + 3)) * 8.0f;
                    } else if (scc == 1) {
                        e0 = (fsig(sv.x) + hf) * 8.0f;
                        e1 = (fsig(sv.y) + hf) * 8.0f;
                        e2 = (fsig(sv.z) + hf) * 8.0f;
                        e3 = (fsig(sv.w) + hf) * 8.0f;
                    } else if (scc == 2) {
                        e0 = fexp(sv.x) * aw; e1 = fexp(sv.y) * aw;
                        e2 = fexp(sv.z) * aw; e3 = fexp(sv.w) * aw;
                    } else if (scc == 3) {
                        e0 = fexp(sv.x) * ah; e1 = fexp(sv.y) * ah;
                        e2 = fexp(sv.z) * ah; e3 = fexp(sv.w) * ah;
                    } else { // scc == 4: conf + unconditional noobj BCE (lg2 units)
                        e0 = fsig(sv.x); e1 = fsig(sv.y);
                        e2 = fsig(sv.z); e3 = fsig(sv.w);
                        lsum += flg2(1.0f - e0) + flg2(1.0f - e1)
                              + flg2(1.0f - e2) + flg2(1.0f - e3);
                    }
                    trow[sbS]           = e0;
                    trow[sbS + NCH]     = e1;
                    trow[sbS + 2 * NCH] = e2;
                    trow[sbS + 3 * NCH] = e3;
                }
            }

            __syncthreads();   // dtile complete

            if (tid == 0) {
                asm volatile("fence.proxy.async.shared::cta;" ::: "memory");
                uint32_t saddr = smem_u32(dbuf);
                asm volatile(
                    "cp.async.bulk.global.shared::cta.bulk_group [%0], [%1], %2;"
                    :: "l"(gdst), "r"(saddr), "r"((uint32_t)DTILE_BYTES) : "memory");
                asm volatile("cp.async.bulk.commit_group;" ::: "memory");
            }

            // advance running pointers
            gdst += DTILEF;
            h0 += 2;
            if (h0 == HH) { h0 = 0; p++; src += (size_t)NCH * HWSZ - (size_t)(HH - 2) * WW; }
            else src += 2 * WW;
        }

        if (tid == 0)
            asm volatile("cp.async.bulk.wait_group 0;" ::: "memory");

        // noobj partial: loss lanes (scc==4) at tids 499..511 = warp 15
        if ((tid >> 5) == 15) {
            #pragma unroll
            for (int off = 16; off; off >>= 1)
                lsum += __shfl_down_sync(0xffffffffu, lsum, off);
            if ((tid & 31) == 0) g_psum[bx] = lsum;
        }
    }

    // -------- last-block election --------
    __syncthreads();
    if (tid == 0) {
        __threadfence();                              // release partials
        s_misc = (atomicAdd(&g_done, 1u) == (unsigned)(gridDim.x - 1));
    }
    __syncthreads();
    if (!s_misc) return;

    // -------- finalize (winning block; tiny) --------
    if (tid == 0) __threadfence();                    // acquire
    __syncthreads();
    {
        double dsum = 0.0;
        if (tid < NWORK) dsum = (double)g_psum[tid];
        #pragma unroll
        for (int off = 16; off; off >>= 1)
            dsum += __shfl_down_sync(0xffffffffu, dsum, off);
        __shared__ double s_d[16];
        if ((tid & 31) == 0) s_d[tid >> 5] = dsum;
        __syncthreads();
        if (tid == 0) {
            double net = 0.0;
            #pragma unroll
            for (int w = 0; w < 16; w++) net += s_d[w];
            net -= (double)g_fin[6];                   // subtract masked cells
            float nobj = fmaxf(g_fin[7], 1.0f);
            float nno  = fmaxf((float)ncells - g_fin[8], 1.0f);
            float noobj_bce = (float)(-(double)LN2 * net / (double)nno);
            float total = (g_fin[0] + g_fin[1] + g_fin[2] + g_fin[3]) / nobj
                        + 1.0f * (g_fin[4] / nobj)
                        + 0.5f * noobj_bce
                        + g_fin[5] / (nobj * (float)NC);
            out[out_size - 1] = total;
            g_done = 0u;                               // reset for next replay
        }
    }
}

// ---------------- launcher ----------------
extern "C" void kernel_launch(void* const* d_in, const int* in_sizes, int n_in,
                              void* d_out, int out_size) {
    const float* x   = (const float*)d_in[0];
    const float* tgt = (const float*)d_in[1];
    float* out = (float*)d_out;

    int B = in_sizes[0] / (AN * NCH * HWSZ);   // 16
    int N = in_sizes[1] / 6;                   // 256
    int ncells = B * AN * HWSZ;                // 129792

    cudaFuncSetAttribute(k_all, cudaFuncAttributeMaxDynamicSharedMemorySize,
                         SMEM_DYN);
    k_all<<<NWORK + 1, TMAIN, SMEM_DYN>>>(x, tgt, out, N, ncells, out_size);
}

// round 16
// speedup vs baseline: 1.6455x; 1.6455x over previous
#include <cuda_runtime.h>
#include <cstdint>

// ---------------- problem constants ----------------
#define AN      3
#define NC      80
#define NCH     85          // C+5
#define HH      52
#define WW      52
#define HWSZ    (HH*WW)     // 2704
#define MAXN    256
#define ROWF4   13          // 52 floats / 4
#define TILEF   (NCH*WW)    // 4420 floats per row tile
#define TMAIN   512
#define NWORK   444         // 3 worker blocks per SM, perfectly balanced
#define CELLS   (16*AN*HWSZ)
#define TILE_BYTES (TILEF*4)     // 17680
#define SPEC0   (TMAIN - 65)     // 447: first special thread (65 special units)

__constant__ float c_aw[AN] = {10.f, 16.f, 33.f};
__constant__ float c_ah[AN] = {13.f, 30.f, 23.f};

// ---------------- device scratch (no allocations allowed) ----------------
__device__ int    g_mask_i[CELLS];   // dedupe scratch (only touched cells used)
__device__ float  g_psum[NWORK];     // per-worker noobj lg2 partials
__device__ float  g_fin[9];          // setup results: sx,sy,sw,sh,conf,cls,fsub,nobj,mcnt
__device__ unsigned int g_done;      // zero at load; winner resets each replay

// ---- fast math helpers ----
#define L2E 1.4426950408889634f
#define LN2 0.6931471805599453f

__device__ __forceinline__ float fex2(float x) {
    float r; asm("ex2.approx.ftz.f32 %0, %1;" : "=f"(r) : "f"(x)); return r;
}
__device__ __forceinline__ float frcp(float x) {
    float r; asm("rcp.approx.ftz.f32 %0, %1;" : "=f"(r) : "f"(x)); return r;
}
__device__ __forceinline__ float flg2(float x) {
    float r; asm("lg2.approx.ftz.f32 %0, %1;" : "=f"(r) : "f"(x)); return r;
}
__device__ __forceinline__ float fsig(float z) { return frcp(1.0f + fex2(-L2E * z)); }
__device__ __forceinline__ float fexp(float z) { return fex2(L2E * z); }

__device__ __forceinline__ uint32_t smem_u32(const void* p) {
    return (uint32_t)__cvta_generic_to_shared(p);
}

// ================= single fused kernel =================
// block 0: setup + target-dependent loss terms (hidden under workers)
// blocks 1..444: 5-6 row tiles each, double-buffered, software-pipelined loads
__global__ __launch_bounds__(TMAIN, 3) void k_all(const float* __restrict__ x,
                                                  const float* __restrict__ t,
                                                  float* __restrict__ out,
                                                  int N, int ncells, int out_size) {
    __shared__ float buf[2 * TILEF];     // double buffer, 35360 B
    __shared__ float s_red[16];
    __shared__ int   s_misc;

    const int tid = threadIdx.x;
    const int bx0 = blockIdx.x;

    if (bx0 == 0) {
        // ======== setup block: targets + all x-only loss terms ========
        __shared__ float acc[8];
        __shared__ int   s_cnt[2];       // mcnt, nobj
        const int n = tid;
        if (n < 8) acc[n] = 0.0f;
        if (n < 2) s_cnt[n] = 0;
        __syncthreads();

        int   cells[4] = {-1, -1, -1, -1};
        int   mycell = -1;
        float ttx = 0.f, tty = 0.f, ttw = 0.f, tth = 0.f;
        int   lab = 0;

        if (n < N) {
            const float* tn = t + 6 * n;
            int   img = (int)tn[0];
            float gx = tn[1] * (float)WW;
            float gy = tn[2] * (float)HH;
            float gw = tn[3] * (float)WW;
            float gh = tn[4] * (float)HH;
            lab = (int)tn[5];

            float iou[AN];
            int best = 0;
            #pragma unroll
            for (int a = 0; a < AN; a++) {
                float aw2 = c_aw[a], ah2 = c_ah[a];
                float inter = fminf(aw2, gw) * fminf(ah2, gh);
                iou[a] = inter / (aw2 * ah2 + 1e-16f + gw * gh - inter);
            }
            if (iou[1] > iou[best]) best = 1;
            if (iou[2] > iou[best]) best = 2;

            int gi = (int)gx;
            int gj = (int)gy;
            mycell = ((img * AN + best) * HH + gj) * WW + gi;

            ttx = gx - floorf(gx);
            tty = gy - floorf(gy);
            ttw = logf(gw / c_aw[best] + 1e-16f);
            tth = logf(gh / c_ah[best] + 1e-16f);

            cells[0] = mycell;
            #pragma unroll
            for (int a = 0; a < AN; a++)
                if (iou[a] > 0.5f)
                    cells[a + 1] = ((img * AN + a) * HH + gj) * WW + gi;

            #pragma unroll
            for (int k = 0; k < 4; k++)
                if (cells[k] >= 0) g_mask_i[cells[k]] = 0;   // re-init each replay
        }
        __syncthreads();

        // unique-masked dedupe + complement subtraction (lg2 units)
        float fsub = 0.0f;
        if (n < N) {
            #pragma unroll
            for (int k = 0; k < 4; k++) {
                if (cells[k] >= 0 && atomicExch(&g_mask_i[cells[k]], 1) == 0) {
                    atomicAdd(&s_cnt[0], 1);
                    int cell = cells[k];
                    int i  = cell % WW;
                    int j  = (cell / WW) % HH;
                    int aa = (cell / HWSZ) % AN;
                    int bb = cell / (AN * HWSZ);
                    float z4 = x[((size_t)((bb * AN + aa) * NCH) + 4) * HWSZ
                                 + (size_t)j * WW + i];
                    fsub += flg2(1.0f - fsig(z4));
                }
            }
        }
        #pragma unroll
        for (int off = 16; off; off >>= 1)
            fsub += __shfl_down_sync(0xffffffffu, fsub, off);
        if ((tid & 31) == 0) s_red[tid >> 5] = fsub;
        __syncthreads();

        // obj-cell last-write-wins dedupe
        if (n < N) atomicMax(&g_mask_i[mycell], 2 + n);
        __syncthreads();

        // obj-cell losses (winners only)
        if (n < N && g_mask_i[mycell] == 2 + n) {
            int cell = mycell;
            int i  = cell % WW;
            int j  = (cell / WW) % HH;
            int aa = (cell / HWSZ) % AN;
            int bb = cell / (AN * HWSZ);
            const float* xb2 = x + ((size_t)(bb * AN + aa) * NCH) * HWSZ
                                 + (size_t)j * WW + i;
            float z0 = xb2[0];
            float z2 = xb2[(size_t)2 * HWSZ];
            float z4 = xb2[(size_t)4 * HWSZ];
            float cx = fsig(z0);
            float dx = cx - ttx;
            float dy = cx - tty;              // reference bug: y-loss uses cx
            float dw = z2 - ttw;
            float dh = z2 - tth;              // reference bug: h-loss uses pw
            float p4 = fmaxf(fsig(z4), 1e-12f);
            float conf = -flg2(p4) * LN2;     // t=1 at obj cell
            float cls = 0.0f;
            #pragma unroll 8
            for (int c = 0; c < NC; c++) {
                float p = fmaxf(fsig(xb2[(size_t)(5 + c) * HWSZ]), 1e-12f);
                cls -= (c == lab) ? flg2(p) * LN2 : flg2(1.0f - p) * LN2;
            }
            atomicAdd(&acc[0], dx * dx);
            atomicAdd(&acc[1], dy * dy);
            atomicAdd(&acc[2], dw * dw);
            atomicAdd(&acc[3], dh * dh);
            atomicAdd(&acc[4], conf);
            atomicAdd(&acc[5], cls);
            atomicAdd(&s_cnt[1], 1);
        }
        __syncthreads();
        if (tid == 0) {
            float fs = 0.0f;
            #pragma unroll
            for (int w = 0; w < 16; w++) fs += s_red[w];
            g_fin[0] = acc[0]; g_fin[1] = acc[1]; g_fin[2] = acc[2];
            g_fin[3] = acc[3]; g_fin[4] = acc[4]; g_fin[5] = acc[5];
            g_fin[6] = fs;                        // fsub (lg2 units)
            g_fin[7] = (float)s_cnt[1];           // nobj
            g_fin[8] = (float)s_cnt[0];           // mcnt
        }
    } else {
        // ======== worker: balanced 5-6 row tiles, pipelined loads ========
        const int bx = bx0 - 1;                 // 0..443
        // blocks 0..275: 6 tiles; 276..443: 5 tiles  (276*6 + 168*5 = 2496)
        const int six = (bx < 276);
        const int cnt = six ? 6 : 5;
        int T = six ? bx * 6 : 1656 + (bx - 276) * 5;

        // per-thread tile-invariant decomposition (R13 mapping)
        int c0 = 5 + tid / ROWF4;
        int w0q = (tid - (c0 - 5) * ROWF4) * 4;
        int g1 = tid + TMAIN;
        int c1 = 5 + g1 / ROWF4;
        int w1q = (g1 - (c1 - 5) * ROWF4) * 4;
        const bool hasX = (tid < 16);           // units 1024..1039
        int g2 = tid + 2 * TMAIN;
        int c2 = 5 + g2 / ROWF4;
        int w2q = (g2 - (c2 - 5) * ROWF4) * 4;

        const int off0 = c0 * HWSZ + w0q;
        const int off1 = c1 * HWSZ + w1q;
        const int off2 = c2 * HWSZ + w2q;
        const int sb0 = w0q * NCH + c0;
        const int sb1 = w1q * NCH + c1;
        const int sb2 = w2q * NCH + c2;

        const bool isSpec = (tid >= SPEC0);
        const int s = tid - SPEC0;
        const int scc = s / ROWF4;
        const int sw0 = (s - scc * ROWF4) * 4;
        const int offS = scc * HWSZ + sw0;
        const int sbS = sw0 * NCH + scc;

        float lsum = 0.0f;

        int h = T % HH;
        int p = T / HH;
        const float* src = x + (size_t)p * (NCH * HWSZ) + (size_t)h * WW;
        float* gdst = out + (size_t)T * TILEF;

        // ---- prologue prefetch: tile 0's two main loads ----
        float4 v0 = *reinterpret_cast<const float4*>(src + off0);
        float4 v1 = *reinterpret_cast<const float4*>(src + off1);

        for (int it = 0; it < cnt; it++) {
            float* trow = buf + (it & 1) * TILEF;

            if (tid == 0 && it >= 2)
                asm volatile("cp.async.bulk.wait_group 1;" ::: "memory");
            __syncthreads();

            // unpipelined secondary loads (16 + 65 threads)
            float4 v2, sv;
            if (hasX)   v2 = *reinterpret_cast<const float4*>(src + off2);
            if (isSpec) sv = *reinterpret_cast<const float4*>(src + offS);

            // capture current tile coords for special path
            const float hf = (float)h;
            const int a = p - (p / AN) * AN;     // p % 3

            // bulk process (v0/v1 already in registers — no exposed latency)
            trow[sb0]           = fsig(v0.x);
            trow[sb0 + NCH]     = fsig(v0.y);
            trow[sb0 + 2 * NCH] = fsig(v0.z);
            trow[sb0 + 3 * NCH] = fsig(v0.w);
            trow[sb1]           = fsig(v1.x);
            trow[sb1 + NCH]     = fsig(v1.y);
            trow[sb1 + 2 * NCH] = fsig(v1.z);
            trow[sb1 + 3 * NCH] = fsig(v1.w);
            if (hasX) {
                trow[sb2]           = fsig(v2.x);
                trow[sb2 + NCH]     = fsig(v2.y);
                trow[sb2 + 2 * NCH] = fsig(v2.z);
                trow[sb2 + 3 * NCH] = fsig(v2.w);
            }

            // special process (65 threads, branchy but tiny)
            if (isSpec) {
                const float aw = c_aw[a], ah = c_ah[a];
                float e0, e1, e2, e3;
                if (scc == 0) {
                    e0 = (fsig(sv.x) + (float)sw0) * 8.0f;
                    e1 = (fsig(sv.y) + (float)(sw0 + 1)) * 8.0f;
                    e2 = (fsig(sv.z) + (float)(sw0 + 2)) * 8.0f;
                    e3 = (fsig(sv.w) + (float)(sw0 + 3)) * 8.0f;
                } else if (scc == 1) {
                    e0 = (fsig(sv.x) + hf) * 8.0f;
                    e1 = (fsig(sv.y) + hf) * 8.0f;
                    e2 = (fsig(sv.z) + hf) * 8.0f;
                    e3 = (fsig(sv.w) + hf) * 8.0f;
                } else if (scc == 2) {
                    e0 = fexp(sv.x) * aw; e1 = fexp(sv.y) * aw;
                    e2 = fexp(sv.z) * aw; e3 = fexp(sv.w) * aw;
                } else if (scc == 3) {
                    e0 = fexp(sv.x) * ah; e1 = fexp(sv.y) * ah;
                    e2 = fexp(sv.z) * ah; e3 = fexp(sv.w) * ah;
                } else { // scc == 4: conf + unconditional noobj BCE (lg2 units)
                    e0 = fsig(sv.x); e1 = fsig(sv.y); e2 = fsig(sv.z); e3 = fsig(sv.w);
                    lsum += flg2(1.0f - e0) + flg2(1.0f - e1)
                          + flg2(1.0f - e2) + flg2(1.0f - e3);
                }
                trow[sbS]           = e0;
                trow[sbS + NCH]     = e1;
                trow[sbS + 2 * NCH] = e2;
                trow[sbS + 3 * NCH] = e3;
            }

            // advance pointers; prefetch next tile's main loads
            h++;
            if (h == HH) { h = 0; p++; src += (size_t)NCH * HWSZ - (size_t)(HH - 1) * WW; }
            else src += WW;
            if (it + 1 < cnt) {
                v0 = *reinterpret_cast<const float4*>(src + off0);
                v1 = *reinterpret_cast<const float4*>(src + off1);
            }

            __syncthreads();   // tile complete

            if (tid == 0) {
                asm volatile("fence.proxy.async.shared::cta;" ::: "memory");
                uint32_t saddr = smem_u32(trow);
                asm volatile(
                    "cp.async.bulk.global.shared::cta.bulk_group [%0], [%1], %2;"
                    :: "l"(gdst), "r"(saddr), "r"((uint32_t)TILE_BYTES) : "memory");
                asm volatile("cp.async.bulk.commit_group;" ::: "memory");
            }
            gdst += TILEF;
        }

        if (tid == 0)
            asm volatile("cp.async.bulk.wait_group 0;" ::: "memory");

        // noobj partial: scc==4 lanes live in warp 15 (tids 499..511)
        if ((tid >> 5) == 15) {
            #pragma unroll
            for (int off = 16; off; off >>= 1)
                lsum += __shfl_down_sync(0xffffffffu, lsum, off);
            if ((tid & 31) == 0) g_psum[bx] = lsum;
        }
    }

    // -------- last-block election --------
    __syncthreads();
    if (tid == 0) {
        __threadfence();                              // release partials
        s_misc = (atomicAdd(&g_done, 1u) == (unsigned)(gridDim.x - 1));
    }
    __syncthreads();
    if (!s_misc) return;

    // -------- finalize (winning block; tiny) --------
    if (tid == 0) __threadfence();                    // acquire
    __syncthreads();
    {
        double dsum = 0.0;
        if (tid < NWORK) dsum = (double)g_psum[tid];
        #pragma unroll
        for (int off = 16; off; off >>= 1)
            dsum += __shfl_down_sync(0xffffffffu, dsum, off);
        __shared__ double s_d[16];
        if ((tid & 31) == 0) s_d[tid >> 5] = dsum;
        __syncthreads();
        if (tid == 0) {
            double net = 0.0;
            #pragma unroll
            for (int w = 0; w < 16; w++) net += s_d[w];
            net -= (double)g_fin[6];                   // subtract masked cells
            float nobj = fmaxf(g_fin[7], 1.0f);
            float nno  = fmaxf((float)ncells - g_fin[8], 1.0f);
            float noobj_bce = (float)(-(double)LN2 * net / (double)nno);
            float total = (g_fin[0] + g_fin[1] + g_fin[2] + g_fin[3]) / nobj
                        + 1.0f * (g_fin[4] / nobj)
                        + 0.5f * noobj_bce
                        + g_fin[5] / (nobj * (float)NC);
            out[out_size - 1] = total;
            g_done = 0u;                               // reset for next replay
        }
    }
}

// ---------------- launcher ----------------
extern "C" void kernel_launch(void* const* d_in, const int* in_sizes, int n_in,
                              void* d_out, int out_size) {
    const float* x   = (const float*)d_in[0];
    const float* tgt = (const float*)d_in[1];
    float* out = (float*)d_out;

    int B = in_sizes[0] / (AN * NCH * HWSZ);   // 16
    int N = in_sizes[1] / 6;                   // 256
    int ncells = B * AN * HWSZ;                // 129792

    k_all<<<NWORK + 1, TMAIN>>>(x, tgt, out, N, ncells, out_size);
}

// round 17
// speedup vs baseline: 1.6534x; 1.0048x over previous
#include <cuda_runtime.h>
#include <cstdint>

// ---------------- problem constants ----------------
#define AN      3
#define NC      80
#define NCH     85          // C+5
#define HH      52
#define WW      52
#define HWSZ    (HH*WW)     // 2704
#define MAXN    256
#define ROWF4   13          // 52 floats / 4
#define TILEF   (NCH*WW)    // 4420 floats per row tile
#define TMAIN   512
#define NWORK   443         // workers; +1 setup block = 444 = exactly 3/SM, 1 wave
#define CELLS   (16*AN*HWSZ)
#define TILE_BYTES (TILEF*4)     // 17680
#define SPEC0   (TMAIN - 65)     // 447: first special thread (65 special units)

__constant__ float c_aw[AN] = {10.f, 16.f, 33.f};
__constant__ float c_ah[AN] = {13.f, 30.f, 23.f};

// ---------------- device scratch (no allocations allowed) ----------------
__device__ int    g_mask_i[CELLS];   // dedupe scratch (only touched cells used)
__device__ float  g_psum[NWORK];     // per-worker noobj lg2 partials
__device__ float  g_fin[9];          // setup results: sx,sy,sw,sh,conf,cls,fsub,nobj,mcnt
__device__ unsigned int g_done;      // zero at load; winner resets each replay

// ---- fast math helpers ----
#define L2E 1.4426950408889634f
#define LN2 0.6931471805599453f

__device__ __forceinline__ float fex2(float x) {
    float r; asm("ex2.approx.ftz.f32 %0, %1;" : "=f"(r) : "f"(x)); return r;
}
__device__ __forceinline__ float frcp(float x) {
    float r; asm("rcp.approx.ftz.f32 %0, %1;" : "=f"(r) : "f"(x)); return r;
}
__device__ __forceinline__ float flg2(float x) {
    float r; asm("lg2.approx.ftz.f32 %0, %1;" : "=f"(r) : "f"(x)); return r;
}
__device__ __forceinline__ float fsig(float z) { return frcp(1.0f + fex2(-L2E * z)); }
__device__ __forceinline__ float fexp(float z) { return fex2(L2E * z); }

__device__ __forceinline__ uint32_t smem_u32(const void* p) {
    return (uint32_t)__cvta_generic_to_shared(p);
}

// ================= single fused kernel (one wave: 444 blocks = 148 SM x 3) ====
// block 0: setup + target-dependent loss terms (hidden under workers)
// blocks 1..443: 5-6 row tiles each, double-buffered, pipelined bulk stores
__global__ __launch_bounds__(TMAIN, 3) void k_all(const float* __restrict__ x,
                                                  const float* __restrict__ t,
                                                  float* __restrict__ out,
                                                  int N, int ncells, int out_size) {
    __shared__ float buf[2 * TILEF];     // double buffer, 35360 B
    __shared__ float s_red[16];
    __shared__ int   s_misc;

    const int tid = threadIdx.x;
    const int bx0 = blockIdx.x;

    if (bx0 == 0) {
        // ======== setup block: targets + all x-only loss terms ========
        __shared__ float acc[8];
        __shared__ int   s_cnt[2];       // mcnt, nobj
        const int n = tid;
        if (n < 8) acc[n] = 0.0f;
        if (n < 2) s_cnt[n] = 0;
        __syncthreads();

        int   cells[4] = {-1, -1, -1, -1};
        int   mycell = -1;
        float ttx = 0.f, tty = 0.f, ttw = 0.f, tth = 0.f;
        int   lab = 0;

        if (n < N) {
            const float* tn = t + 6 * n;
            int   img = (int)tn[0];
            float gx = tn[1] * (float)WW;
            float gy = tn[2] * (float)HH;
            float gw = tn[3] * (float)WW;
            float gh = tn[4] * (float)HH;
            lab = (int)tn[5];

            float iou[AN];
            int best = 0;
            #pragma unroll
            for (int a = 0; a < AN; a++) {
                float aw2 = c_aw[a], ah2 = c_ah[a];
                float inter = fminf(aw2, gw) * fminf(ah2, gh);
                iou[a] = inter / (aw2 * ah2 + 1e-16f + gw * gh - inter);
            }
            if (iou[1] > iou[best]) best = 1;
            if (iou[2] > iou[best]) best = 2;

            int gi = (int)gx;
            int gj = (int)gy;
            mycell = ((img * AN + best) * HH + gj) * WW + gi;

            ttx = gx - floorf(gx);
            tty = gy - floorf(gy);
            ttw = logf(gw / c_aw[best] + 1e-16f);
            tth = logf(gh / c_ah[best] + 1e-16f);

            cells[0] = mycell;
            #pragma unroll
            for (int a = 0; a < AN; a++)
                if (iou[a] > 0.5f)
                    cells[a + 1] = ((img * AN + a) * HH + gj) * WW + gi;

            #pragma unroll
            for (int k = 0; k < 4; k++)
                if (cells[k] >= 0) g_mask_i[cells[k]] = 0;   // re-init each replay
        }
        __syncthreads();

        // unique-masked dedupe + complement subtraction (lg2 units)
        float fsub = 0.0f;
        if (n < N) {
            #pragma unroll
            for (int k = 0; k < 4; k++) {
                if (cells[k] >= 0 && atomicExch(&g_mask_i[cells[k]], 1) == 0) {
                    atomicAdd(&s_cnt[0], 1);
                    int cell = cells[k];
                    int i  = cell % WW;
                    int j  = (cell / WW) % HH;
                    int aa = (cell / HWSZ) % AN;
                    int bb = cell / (AN * HWSZ);
                    float z4 = x[((size_t)((bb * AN + aa) * NCH) + 4) * HWSZ
                                 + (size_t)j * WW + i];
                    fsub += flg2(1.0f - fsig(z4));
                }
            }
        }
        #pragma unroll
        for (int off = 16; off; off >>= 1)
            fsub += __shfl_down_sync(0xffffffffu, fsub, off);
        if ((tid & 31) == 0) s_red[tid >> 5] = fsub;
        __syncthreads();

        // obj-cell last-write-wins dedupe
        if (n < N) atomicMax(&g_mask_i[mycell], 2 + n);
        __syncthreads();

        // obj-cell losses (winners only)
        if (n < N && g_mask_i[mycell] == 2 + n) {
            int cell = mycell;
            int i  = cell % WW;
            int j  = (cell / WW) % HH;
            int aa = (cell / HWSZ) % AN;
            int bb = cell / (AN * HWSZ);
            const float* xb2 = x + ((size_t)(bb * AN + aa) * NCH) * HWSZ
                                 + (size_t)j * WW + i;
            float z0 = xb2[0];
            float z2 = xb2[(size_t)2 * HWSZ];
            float z4 = xb2[(size_t)4 * HWSZ];
            float cx = fsig(z0);
            float dx = cx - ttx;
            float dy = cx - tty;              // reference bug: y-loss uses cx
            float dw = z2 - ttw;
            float dh = z2 - tth;              // reference bug: h-loss uses pw
            float p4 = fmaxf(fsig(z4), 1e-12f);
            float conf = -flg2(p4) * LN2;     // t=1 at obj cell
            float cls = 0.0f;
            #pragma unroll 8
            for (int c = 0; c < NC; c++) {
                float p = fmaxf(fsig(xb2[(size_t)(5 + c) * HWSZ]), 1e-12f);
                cls -= (c == lab) ? flg2(p) * LN2 : flg2(1.0f - p) * LN2;
            }
            atomicAdd(&acc[0], dx * dx);
            atomicAdd(&acc[1], dy * dy);
            atomicAdd(&acc[2], dw * dw);
            atomicAdd(&acc[3], dh * dh);
            atomicAdd(&acc[4], conf);
            atomicAdd(&acc[5], cls);
            atomicAdd(&s_cnt[1], 1);
        }
        __syncthreads();
        if (tid == 0) {
            float fs = 0.0f;
            #pragma unroll
            for (int w = 0; w < 16; w++) fs += s_red[w];
            g_fin[0] = acc[0]; g_fin[1] = acc[1]; g_fin[2] = acc[2];
            g_fin[3] = acc[3]; g_fin[4] = acc[4]; g_fin[5] = acc[5];
            g_fin[6] = fs;                        // fsub (lg2 units)
            g_fin[7] = (float)s_cnt[1];           // nobj
            g_fin[8] = (float)s_cnt[0];           // mcnt
        }
    } else {
        // ======== worker: balanced 5-6 consecutive row tiles ========
        const int bx = bx0 - 1;                 // 0..442
        // blocks 0..280: 6 tiles; 281..442: 5 tiles  (281*6 + 162*5 = 2496)
        const int six = (bx < 281);
        const int cnt = six ? 6 : 5;
        int T = six ? bx * 6 : 1686 + (bx - 281) * 5;

        // per-thread tile-invariant decomposition (R13 mapping)
        int c0 = 5 + tid / ROWF4;
        int w0q = (tid - (c0 - 5) * ROWF4) * 4;
        int g1 = tid + TMAIN;
        int c1 = 5 + g1 / ROWF4;
        int w1q = (g1 - (c1 - 5) * ROWF4) * 4;
        const bool hasX = (tid < 16);           // units 1024..1039
        int g2 = tid + 2 * TMAIN;
        int c2 = 5 + g2 / ROWF4;
        int w2q = (g2 - (c2 - 5) * ROWF4) * 4;

        const int off0 = c0 * HWSZ + w0q;
        const int off1 = c1 * HWSZ + w1q;
        const int off2 = c2 * HWSZ + w2q;
        const int sb0 = w0q * NCH + c0;
        const int sb1 = w1q * NCH + c1;
        const int sb2 = w2q * NCH + c2;

        const bool isSpec = (tid >= SPEC0);
        const int s = tid - SPEC0;
        const int scc = s / ROWF4;
        const int sw0 = (s - scc * ROWF4) * 4;
        const int offS = scc * HWSZ + sw0;
        const int sbS = sw0 * NCH + scc;

        float lsum = 0.0f;

        int h = T % HH;
        int p = T / HH;
        const float* src = x + (size_t)p * (NCH * HWSZ) + (size_t)h * WW;
        float* gdst = out + (size_t)T * TILEF;

        for (int it = 0; it < cnt; it++) {
            float* trow = buf + (it & 1) * TILEF;

            if (tid == 0 && it >= 2)
                asm volatile("cp.async.bulk.wait_group 1;" ::: "memory");
            __syncthreads();

            // loads
            float4 v0 = *reinterpret_cast<const float4*>(src + off0);
            float4 v1 = *reinterpret_cast<const float4*>(src + off1);
            float4 v2, sv;
            if (hasX)   v2 = *reinterpret_cast<const float4*>(src + off2);
            if (isSpec) sv = *reinterpret_cast<const float4*>(src + offS);

            // bulk process (branchless)
            trow[sb0]           = fsig(v0.x);
            trow[sb0 + NCH]     = fsig(v0.y);
            trow[sb0 + 2 * NCH] = fsig(v0.z);
            trow[sb0 + 3 * NCH] = fsig(v0.w);
            trow[sb1]           = fsig(v1.x);
            trow[sb1 + NCH]     = fsig(v1.y);
            trow[sb1 + 2 * NCH] = fsig(v1.z);
            trow[sb1 + 3 * NCH] = fsig(v1.w);
            if (hasX) {
                trow[sb2]           = fsig(v2.x);
                trow[sb2 + NCH]     = fsig(v2.y);
                trow[sb2 + 2 * NCH] = fsig(v2.z);
                trow[sb2 + 3 * NCH] = fsig(v2.w);
            }

            // special process (65 threads)
            if (isSpec) {
                const float hf = (float)h;
                const int a = p - (p / AN) * AN;     // p % 3
                const float aw = c_aw[a], ah = c_ah[a];
                float e0, e1, e2, e3;
                if (scc == 0) {
                    e0 = (fsig(sv.x) + (float)sw0) * 8.0f;
                    e1 = (fsig(sv.y) + (float)(sw0 + 1)) * 8.0f;
                    e2 = (fsig(sv.z) + (float)(sw0 + 2)) * 8.0f;
                    e3 = (fsig(sv.w) + (float)(sw0 + 3)) * 8.0f;
                } else if (scc == 1) {
                    e0 = (fsig(sv.x) + hf) * 8.0f;
                    e1 = (fsig(sv.y) + hf) * 8.0f;
                    e2 = (fsig(sv.z) + hf) * 8.0f;
                    e3 = (fsig(sv.w) + hf) * 8.0f;
                } else if (scc == 2) {
                    e0 = fexp(sv.x) * aw; e1 = fexp(sv.y) * aw;
                    e2 = fexp(sv.z) * aw; e3 = fexp(sv.w) * aw;
                } else if (scc == 3) {
                    e0 = fexp(sv.x) * ah; e1 = fexp(sv.y) * ah;
                    e2 = fexp(sv.z) * ah; e3 = fexp(sv.w) * ah;
                } else { // scc == 4: conf + unconditional noobj BCE (lg2 units)
                    e0 = fsig(sv.x); e1 = fsig(sv.y); e2 = fsig(sv.z); e3 = fsig(sv.w);
                    lsum += flg2(1.0f - e0) + flg2(1.0f - e1)
                          + flg2(1.0f - e2) + flg2(1.0f - e3);
                }
                trow[sbS]           = e0;
                trow[sbS + NCH]     = e1;
                trow[sbS + 2 * NCH] = e2;
                trow[sbS + 3 * NCH] = e3;
            }

            __syncthreads();   // tile complete

            if (tid == 0) {
                asm volatile("fence.proxy.async.shared::cta;" ::: "memory");
                uint32_t saddr = smem_u32(trow);
                asm volatile(
                    "cp.async.bulk.global.shared::cta.bulk_group [%0], [%1], %2;"
                    :: "l"(gdst), "r"(saddr), "r"((uint32_t)TILE_BYTES) : "memory");
                asm volatile("cp.async.bulk.commit_group;" ::: "memory");
            }

            // advance running pointers
            gdst += TILEF;
            h++;
            if (h == HH) { h = 0; p++; src += (size_t)NCH * HWSZ - (size_t)(HH - 1) * WW; }
            else src += WW;
        }

        if (tid == 0)
            asm volatile("cp.async.bulk.wait_group 0;" ::: "memory");

        // noobj partial: scc==4 lanes live in warp 15 (tids 499..511)
        if ((tid >> 5) == 15) {
            #pragma unroll
            for (int off = 16; off; off >>= 1)
                lsum += __shfl_down_sync(0xffffffffu, lsum, off);
            if ((tid & 31) == 0) g_psum[bx] = lsum;
        }
    }

    // -------- last-block election --------
    __syncthreads();
    if (tid == 0) {
        __threadfence();                              // release partials
        s_misc = (atomicAdd(&g_done, 1u) == (unsigned)(gridDim.x - 1));
    }
    __syncthreads();
    if (!s_misc) return;

    // -------- finalize (winning block; tiny) --------
    if (tid == 0) __threadfence();                    // acquire
    __syncthreads();
    {
        double dsum = 0.0;
        if (tid < NWORK) dsum = (double)g_psum[tid];
        #pragma unroll
        for (int off = 16; off; off >>= 1)
            dsum += __shfl_down_sync(0xffffffffu, dsum, off);
        __shared__ double s_d[16];
        if ((tid & 31) == 0) s_d[tid >> 5] = dsum;
        __syncthreads();
        if (tid == 0) {
            double net = 0.0;
            #pragma unroll
            for (int w = 0; w < 16; w++) net += s_d[w];
            net -= (double)g_fin[6];                   // subtract masked cells
            float nobj = fmaxf(g_fin[7], 1.0f);
            float nno  = fmaxf((float)ncells - g_fin[8], 1.0f);
            float noobj_bce = (float)(-(double)LN2 * net / (double)nno);
            float total = (g_fin[0] + g_fin[1] + g_fin[2] + g_fin[3]) / nobj
                        + 1.0f * (g_fin[4] / nobj)
                        + 0.5f * noobj_bce
                        + g_fin[5] / (nobj * (float)NC);
            out[out_size - 1] = total;
            g_done = 0u;                               // reset for next replay
        }
    }
}

// ---------------- launcher ----------------
extern "C" void kernel_launch(void* const* d_in, const int* in_sizes, int n_in,
                              void* d_out, int out_size) {
    const float* x   = (const float*)d_in[0];
    const float* tgt = (const float*)d_in[1];
    float* out = (float*)d_out;

    int B = in_sizes[0] / (AN * NCH * HWSZ);   // 16
    int N = in_sizes[1] / 6;                   // 256
    int ncells = B * AN * HWSZ;                // 129792

    k_all<<<NWORK + 1, TMAIN>>>(x, tgt, out, N, ncells, out_size);
}